// round 5
// baseline (speedup 1.0000x reference)
#include <cuda_runtime.h>
#include <cuda_bf16.h>
#include <cstdint>

// Problem constants (AttentionLayer: N=4, S=T=2048, D=1024)
#define NB 4
#define SQ 2048
#define TK 2048
#define DD 1024

// Scratch (allocation-free rule: __device__ globals)
static __device__ float g_q[NB * SQ * DD];
static __device__ float g_k[NB * TK * DD];
static __device__ float g_v[NB * TK * DD];
static __device__ float g_s[(size_t)NB * SQ * TK];

// ---------------------------------------------------------------------------
// TF32 split helpers. x = hi + lo with hi = tf32(x), lo = tf32(x - hi).
// 3 MMAs (lo*hi + hi*lo + hi*hi) give ~2^-21 accuracy (~fp32). Split is done
// ONCE per tile in the loader; smem holds interleaved (hi,lo) pairs so the
// inner loop is pure LDS.64 + HMMA.
// ---------------------------------------------------------------------------
__device__ __forceinline__ uint32_t f2tf32(float x) {
    uint32_t r;
    asm("cvt.rna.tf32.f32 %0, %1;" : "=r"(r) : "f"(x));
    return r;
}
__device__ __forceinline__ uint2 tf32_split2(float x) {
    uint2 p;
    p.x = f2tf32(x);
    p.y = f2tf32(x - __uint_as_float(p.x));
    return p;
}
// Split 4 consecutive elements and store as two 16B smem writes.
__device__ __forceinline__ void split_store4(uint2* dst, float4 f) {
    uint2 s0 = tf32_split2(f.x), s1 = tf32_split2(f.y);
    uint2 s2 = tf32_split2(f.z), s3 = tf32_split2(f.w);
    *(uint4*)(dst)     = make_uint4(s0.x, s0.y, s1.x, s1.y);
    *(uint4*)(dst + 2) = make_uint4(s2.x, s2.y, s3.x, s3.y);
}

#define MMA_TF32(c, a0, a1, a2, a3, b0, b1)                            \
    asm volatile(                                                      \
        "mma.sync.aligned.m16n8k8.row.col.f32.tf32.tf32.f32 "          \
        "{%0,%1,%2,%3}, {%4,%5,%6,%7}, {%8,%9}, {%0,%1,%2,%3};"        \
        : "+f"(c[0]), "+f"(c[1]), "+f"(c[2]), "+f"(c[3])               \
        : "r"(a0), "r"(a1), "r"(a2), "r"(a3), "r"(b0), "r"(b1))

// ---------------------------------------------------------------------------
// Warp-tile compute, A m-major [128][18], B n-major [128][18] (k16 chunk).
// 8 warps: warp_m in {0,1}, warp_n in {0..3}; warp tile 64x32 = 4x4 atoms.
// ---------------------------------------------------------------------------
__device__ __forceinline__ void mma_compute_mn(
    const uint2 (*__restrict__ As)[18], const uint2 (*__restrict__ Bs)[18],
    float acc[4][4][4], int warp_m, int warp_n, int g, int t4)
{
    #pragma unroll
    for (int k8 = 0; k8 < 16; k8 += 8) {
        uint2 b0[4], b1[4];
        #pragma unroll
        for (int j = 0; j < 4; j++) {
            const int nn = warp_n * 32 + j * 8 + g;
            b0[j] = Bs[nn][k8 + t4];
            b1[j] = Bs[nn][k8 + t4 + 4];
        }
        #pragma unroll
        for (int i = 0; i < 4; i++) {
            const int m = warp_m * 64 + i * 16;
            uint2 a0 = As[m + g][k8 + t4];
            uint2 a1 = As[m + g + 8][k8 + t4];
            uint2 a2 = As[m + g][k8 + t4 + 4];
            uint2 a3 = As[m + g + 8][k8 + t4 + 4];
            #pragma unroll
            for (int j = 0; j < 4; j++) {
                MMA_TF32(acc[i][j], a0.y, a1.y, a2.y, a3.y, b0[j].x, b1[j].x);
                MMA_TF32(acc[i][j], a0.x, a1.x, a2.x, a3.x, b0[j].y, b1[j].y);
                MMA_TF32(acc[i][j], a0.x, a1.x, a2.x, a3.x, b0[j].x, b1[j].x);
            }
        }
    }
}

// Store warp accumulators (m16n8k8 D layout: c0,c1 row g; c2,c3 row g+8).
__device__ __forceinline__ void mma_tile_store(
    float* __restrict__ C, int ldc, int m0, int n0,
    float acc[4][4][4], int warp_m, int warp_n, int lane, float scale)
{
    const int g  = lane >> 2;
    const int t4 = lane & 3;
    #pragma unroll
    for (int i = 0; i < 4; i++) {
        #pragma unroll
        for (int j = 0; j < 4; j++) {
            const int r0 = m0 + warp_m * 64 + i * 16 + g;
            const int c0 = n0 + warp_n * 32 + j * 8 + t4 * 2;
            *(float2*)(C + (size_t)r0 * ldc + c0) =
                make_float2(acc[i][j][0] * scale, acc[i][j][1] * scale);
            *(float2*)(C + (size_t)(r0 + 8) * ldc + c0) =
                make_float2(acc[i][j][2] * scale, acc[i][j][3] * scale);
        }
    }
}

// ---------------------------------------------------------------------------
// GEMM, both operands K-major: C[m][n] = scale * sum_k A[m][k]*B[n][k]
// Register-prefetch pipeline: store chunk i, issue LDG for chunk i+1, compute.
// ---------------------------------------------------------------------------
__device__ __forceinline__ void gemm128_kk_mma(
    const float* __restrict__ A, const float* __restrict__ B, float* __restrict__ C,
    int lda, int ldb, int ldc, int K, int m0, int n0, float scale)
{
    __shared__ __align__(16) uint2 As[128][18];   // m-major, (hi,lo) per k
    __shared__ __align__(16) uint2 Bs[128][18];   // n-major, (hi,lo) per k

    const int tid    = threadIdx.x;
    const int lane   = tid & 31;
    const int g      = lane >> 2;
    const int t4     = lane & 3;
    const int wid    = tid >> 5;
    const int warp_m = wid & 1;
    const int warp_n = wid >> 1;
    const int lr     = tid >> 2;        // 0..63 loader row
    const int lk     = (tid & 3) << 2;  // 0,4,8,12 loader k offset

    float acc[4][4][4] = {};

    const float* Ap0 = A + (size_t)(m0 + lr)      * lda + lk;
    const float* Ap1 = A + (size_t)(m0 + 64 + lr) * lda + lk;
    const float* Bp0 = B + (size_t)(n0 + lr)      * ldb + lk;
    const float* Bp1 = B + (size_t)(n0 + 64 + lr) * ldb + lk;

    float4 a0 = *(const float4*)(Ap0);
    float4 a1 = *(const float4*)(Ap1);
    float4 b0 = *(const float4*)(Bp0);
    float4 b1 = *(const float4*)(Bp1);

    for (int k0 = 0; k0 < K; k0 += 16) {
        __syncthreads();   // previous iteration's compute done reading smem
        split_store4(&As[lr][lk],      a0);
        split_store4(&As[lr + 64][lk], a1);
        split_store4(&Bs[lr][lk],      b0);
        split_store4(&Bs[lr + 64][lk], b1);
        __syncthreads();

        if (k0 + 16 < K) {     // prefetch next chunk; overlaps with MMAs below
            a0 = *(const float4*)(Ap0 + k0 + 16);
            a1 = *(const float4*)(Ap1 + k0 + 16);
            b0 = *(const float4*)(Bp0 + k0 + 16);
            b1 = *(const float4*)(Bp1 + k0 + 16);
        }

        mma_compute_mn(As, Bs, acc, warp_m, warp_n, g, t4);
    }
    mma_tile_store(C, ldc, m0, n0, acc, warp_m, warp_n, lane, scale);
}

// ---------------------------------------------------------------------------
// Kernel 1: Q/K/V projections. y = x @ W^T (W row-major [out,in] => K-major)
// ---------------------------------------------------------------------------
__global__ void __launch_bounds__(256, 2)
proj_kernel(const float* __restrict__ q, const float* __restrict__ k,
            const float* __restrict__ v, const float* __restrict__ wq,
            const float* __restrict__ wk, const float* __restrict__ wv)
{
    const float* X; const float* W; float* Y;
    if (blockIdx.z == 0)      { X = q; W = wq; Y = g_q; }
    else if (blockIdx.z == 1) { X = k; W = wk; Y = g_k; }
    else                      { X = v; W = wv; Y = g_v; }
    gemm128_kk_mma(X, W, Y, DD, DD, DD, DD, blockIdx.y * 128, blockIdx.x * 128, 1.0f);
}

// ---------------------------------------------------------------------------
// Kernel 2: logits S = (q @ k^T)/sqrt(D); skip tiles above causal diagonal.
// ---------------------------------------------------------------------------
__global__ void __launch_bounds__(256, 2)
scores_kernel()
{
    const int m0 = blockIdx.y * 128;
    const int n0 = blockIdx.x * 128;
    if (n0 > m0) return;               // fully masked tile
    const int n = blockIdx.z;
    gemm128_kk_mma(g_q + (size_t)n * SQ * DD,
                   g_k + (size_t)n * TK * DD,
                   g_s + (size_t)n * SQ * TK,
                   DD, DD, TK, DD, m0, n0, 0.03125f /* 1/sqrt(1024) */);
}

// ---------------------------------------------------------------------------
// Kernel 3: causal row softmax in place; zeros above the diagonal (including
// tiles scores_kernel skipped), so PV can read whole tiles.
// ---------------------------------------------------------------------------
__global__ void __launch_bounds__(256)
softmax_kernel()
{
    __shared__ float red[8];
    const int row = blockIdx.x;             // 0 .. NB*SQ-1
    const int s   = row & (SQ - 1);
    const int len = s + 1;
    float* x = g_s + (size_t)row * TK;
    const int tid = threadIdx.x;

    float vals[TK / 256];
    float m = -3.0e38f;
    #pragma unroll
    for (int i = 0; i < TK / 256; i++) {
        int j = tid + i * 256;
        vals[i] = (j < len) ? x[j] : -3.0e38f;
        m = fmaxf(m, vals[i]);
    }
    #pragma unroll
    for (int o = 16; o; o >>= 1) m = fmaxf(m, __shfl_xor_sync(0xffffffffu, m, o));
    if ((tid & 31) == 0) red[tid >> 5] = m;
    __syncthreads();
    m = red[0];
    #pragma unroll
    for (int w = 1; w < 8; w++) m = fmaxf(m, red[w]);
    __syncthreads();

    float sum = 0.f;
    #pragma unroll
    for (int i = 0; i < TK / 256; i++) {
        int j = tid + i * 256;
        float e = (j < len) ? expf(vals[i] - m) : 0.f;
        vals[i] = e;
        sum += e;
    }
    #pragma unroll
    for (int o = 16; o; o >>= 1) sum += __shfl_xor_sync(0xffffffffu, sum, o);
    if ((tid & 31) == 0) red[tid >> 5] = sum;
    __syncthreads();
    float tot = red[0];
    #pragma unroll
    for (int w = 1; w < 8; w++) tot += red[w];
    const float inv = 1.0f / tot;

    #pragma unroll
    for (int i = 0; i < TK / 256; i++) {
        int j = tid + i * 256;
        x[j] = vals[i] * inv;
    }
}

// ---------------------------------------------------------------------------
// Kernel 4: O = P @ V. P=[SQ,TK] K-major -> As m-major; V=[TK,DD] k-major
// smem Bs[16][132]. K-loop stops at m0+128 (probs beyond are exactly 0).
// ---------------------------------------------------------------------------
__global__ void __launch_bounds__(256, 2)
pv_kernel(float* __restrict__ out)
{
    __shared__ __align__(16) uint2 As[128][18];   // m-major (hi,lo)
    __shared__ __align__(16) uint2 Bs[16][132];   // k-major (hi,lo)

    const int n  = blockIdx.z;
    const int m0 = blockIdx.y * 128;
    const int n0 = blockIdx.x * 128;
    const float* A = g_s + (size_t)n * SQ * TK;
    const float* B = g_v + (size_t)n * TK * DD;
    float*       C = out + (size_t)n * SQ * DD;
    const int Kend = m0 + 128;

    const int tid    = threadIdx.x;
    const int lane   = tid & 31;
    const int g      = lane >> 2;
    const int t4     = lane & 3;
    const int wid    = tid >> 5;
    const int warp_m = wid & 1;
    const int warp_n = wid >> 1;
    const int lr     = tid >> 2;
    const int lk     = (tid & 3) << 2;
    const int br     = tid >> 5;         // 0..7
    const int bc     = (tid & 31) << 2;  // 0..124

    float acc[4][4][4] = {};

    const float* Ap0 = A + (size_t)(m0 + lr)      * TK + lk;
    const float* Ap1 = A + (size_t)(m0 + 64 + lr) * TK + lk;
    const float* Bp0 = B + (size_t)br       * DD + n0 + bc;
    const float* Bp1 = B + (size_t)(br + 8) * DD + n0 + bc;

    float4 a0 = *(const float4*)(Ap0);
    float4 a1 = *(const float4*)(Ap1);
    float4 v0 = *(const float4*)(Bp0);
    float4 v1 = *(const float4*)(Bp1);

    for (int k0 = 0; k0 < Kend; k0 += 16) {
        __syncthreads();
        split_store4(&As[lr][lk],      a0);
        split_store4(&As[lr + 64][lk], a1);
        split_store4(&Bs[br][bc],      v0);
        split_store4(&Bs[br + 8][bc],  v1);
        __syncthreads();

        if (k0 + 16 < Kend) {   // prefetch next chunk
            a0 = *(const float4*)(Ap0 + k0 + 16);
            a1 = *(const float4*)(Ap1 + k0 + 16);
            v0 = *(const float4*)(Bp0 + (size_t)(k0 + 16) * DD);
            v1 = *(const float4*)(Bp1 + (size_t)(k0 + 16) * DD);
        }

        // inline compute with k-major B
        #pragma unroll
        for (int k8 = 0; k8 < 16; k8 += 8) {
            uint2 b0[4], b1[4];
            #pragma unroll
            for (int j = 0; j < 4; j++) {
                const int nn = warp_n * 32 + j * 8 + g;
                b0[j] = Bs[k8 + t4][nn];
                b1[j] = Bs[k8 + t4 + 4][nn];
            }
            #pragma unroll
            for (int i = 0; i < 4; i++) {
                const int m = warp_m * 64 + i * 16;
                uint2 fa0 = As[m + g][k8 + t4];
                uint2 fa1 = As[m + g + 8][k8 + t4];
                uint2 fa2 = As[m + g][k8 + t4 + 4];
                uint2 fa3 = As[m + g + 8][k8 + t4 + 4];
                #pragma unroll
                for (int j = 0; j < 4; j++) {
                    MMA_TF32(acc[i][j], fa0.y, fa1.y, fa2.y, fa3.y, b0[j].x, b1[j].x);
                    MMA_TF32(acc[i][j], fa0.x, fa1.x, fa2.x, fa3.x, b0[j].y, b1[j].y);
                    MMA_TF32(acc[i][j], fa0.x, fa1.x, fa2.x, fa3.x, b0[j].x, b1[j].x);
                }
            }
        }
    }
    mma_tile_store(C, DD, m0, n0, acc, warp_m, warp_n, lane, 1.0f);
}

// ---------------------------------------------------------------------------
// Inputs (metadata order): query, key, value, attn_mask (int32 tril — causal
// by construction, handled analytically), Wq, Wk, Wv. Output fp32 [4,2048,1024].
// ---------------------------------------------------------------------------
extern "C" void kernel_launch(void* const* d_in, const int* in_sizes, int n_in,
                              void* d_out, int out_size)
{
    const float* q  = (const float*)d_in[0];
    const float* k  = (const float*)d_in[1];
    const float* v  = (const float*)d_in[2];
    const float* wq = (const float*)d_in[4];
    const float* wk = (const float*)d_in[5];
    const float* wv = (const float*)d_in[6];
    float* out = (float*)d_out;

    proj_kernel<<<dim3(DD / 128, (NB * SQ) / 128, 3), 256>>>(q, k, v, wq, wk, wv);
    scores_kernel<<<dim3(TK / 128, SQ / 128, NB), 256>>>();
    softmax_kernel<<<dim3(NB * SQ), 256>>>();
    pv_kernel<<<dim3(DD / 128, SQ / 128, NB), 256>>>(out);
}

// round 6
// speedup vs baseline: 1.0116x; 1.0116x over previous
#include <cuda_runtime.h>
#include <cuda_bf16.h>
#include <cstdint>

// Problem constants (AttentionLayer: N=4, S=T=2048, D=1024)
#define NB 4
#define SQ 2048
#define TK 2048
#define DD 1024

// Scratch (allocation-free rule: __device__ globals)
static __device__ float g_q[NB * SQ * DD];
static __device__ float g_k[NB * TK * DD];
static __device__ float g_v[NB * TK * DD];
static __device__ float g_s[(size_t)NB * SQ * TK];

// ---------------------------------------------------------------------------
// TF32 split helpers. x = hi + lo with hi = tf32(x), lo = tf32(x - hi).
// 3 MMAs (lo*hi + hi*lo + hi*hi) give ~2^-21 accuracy (~fp32). Split is done
// ONCE per tile in the loader; smem holds interleaved (hi,lo) pairs so the
// inner loop is pure LDS.64 + HMMA.
// Row stride 20 uint2 (=40 words): fragment reads hit banks (8g+2t4) mod 32,
// a bijection per half-warp -> conflict-free LDS.64.
// ---------------------------------------------------------------------------
#define AW 20   // padded row stride (uint2 units) for m-/n-major smem arrays

__device__ __forceinline__ uint32_t f2tf32(float x) {
    uint32_t r;
    asm("cvt.rna.tf32.f32 %0, %1;" : "=r"(r) : "f"(x));
    return r;
}
__device__ __forceinline__ uint2 tf32_split2(float x) {
    uint2 p;
    p.x = f2tf32(x);
    p.y = f2tf32(x - __uint_as_float(p.x));
    return p;
}
// Split 4 consecutive elements and store as two 16B smem writes.
__device__ __forceinline__ void split_store4(uint2* dst, float4 f) {
    uint2 s0 = tf32_split2(f.x), s1 = tf32_split2(f.y);
    uint2 s2 = tf32_split2(f.z), s3 = tf32_split2(f.w);
    *(uint4*)(dst)     = make_uint4(s0.x, s0.y, s1.x, s1.y);
    *(uint4*)(dst + 2) = make_uint4(s2.x, s2.y, s3.x, s3.y);
}

#define MMA_TF32(c, a0, a1, a2, a3, b0, b1)                            \
    asm volatile(                                                      \
        "mma.sync.aligned.m16n8k8.row.col.f32.tf32.tf32.f32 "          \
        "{%0,%1,%2,%3}, {%4,%5,%6,%7}, {%8,%9}, {%0,%1,%2,%3};"        \
        : "+f"(c[0]), "+f"(c[1]), "+f"(c[2]), "+f"(c[3])               \
        : "r"(a0), "r"(a1), "r"(a2), "r"(a3), "r"(b0), "r"(b1))

// ---------------------------------------------------------------------------
// Warp-tile compute, A m-major [128][AW], B n-major [128][AW] (k16 chunk).
// 8 warps: warp_m in {0,1}, warp_n in {0..3}; warp tile 64x32 = 4x4 atoms.
// ---------------------------------------------------------------------------
__device__ __forceinline__ void mma_compute_mn(
    const uint2 (*__restrict__ As)[AW], const uint2 (*__restrict__ Bs)[AW],
    float acc[4][4][4], int warp_m, int warp_n, int g, int t4)
{
    #pragma unroll
    for (int k8 = 0; k8 < 16; k8 += 8) {
        uint2 b0[4], b1[4];
        #pragma unroll
        for (int j = 0; j < 4; j++) {
            const int nn = warp_n * 32 + j * 8 + g;
            b0[j] = Bs[nn][k8 + t4];
            b1[j] = Bs[nn][k8 + t4 + 4];
        }
        #pragma unroll
        for (int i = 0; i < 4; i++) {
            const int m = warp_m * 64 + i * 16;
            uint2 a0 = As[m + g][k8 + t4];
            uint2 a1 = As[m + g + 8][k8 + t4];
            uint2 a2 = As[m + g][k8 + t4 + 4];
            uint2 a3 = As[m + g + 8][k8 + t4 + 4];
            #pragma unroll
            for (int j = 0; j < 4; j++) {
                MMA_TF32(acc[i][j], a0.y, a1.y, a2.y, a3.y, b0[j].x, b1[j].x);
                MMA_TF32(acc[i][j], a0.x, a1.x, a2.x, a3.x, b0[j].y, b1[j].y);
                MMA_TF32(acc[i][j], a0.x, a1.x, a2.x, a3.x, b0[j].x, b1[j].x);
            }
        }
    }
}

// Store warp accumulators (m16n8k8 D layout: c0,c1 row g; c2,c3 row g+8).
__device__ __forceinline__ void mma_tile_store(
    float* __restrict__ C, int ldc, int m0, int n0,
    float acc[4][4][4], int warp_m, int warp_n, int lane, float scale)
{
    const int g  = lane >> 2;
    const int t4 = lane & 3;
    #pragma unroll
    for (int i = 0; i < 4; i++) {
        #pragma unroll
        for (int j = 0; j < 4; j++) {
            const int r0 = m0 + warp_m * 64 + i * 16 + g;
            const int c0 = n0 + warp_n * 32 + j * 8 + t4 * 2;
            *(float2*)(C + (size_t)r0 * ldc + c0) =
                make_float2(acc[i][j][0] * scale, acc[i][j][1] * scale);
            *(float2*)(C + (size_t)(r0 + 8) * ldc + c0) =
                make_float2(acc[i][j][2] * scale, acc[i][j][3] * scale);
        }
    }
}

// ---------------------------------------------------------------------------
// GEMM, both operands K-major: C[m][n] = scale * sum_k A[m][k]*B[n][k]
// Register-prefetch pipeline: store chunk i, issue LDG for chunk i+1, compute.
// ---------------------------------------------------------------------------
__device__ __forceinline__ void gemm128_kk_mma(
    const float* __restrict__ A, const float* __restrict__ B, float* __restrict__ C,
    int lda, int ldb, int ldc, int K, int m0, int n0, float scale)
{
    __shared__ __align__(16) uint2 As[128][AW];   // m-major, (hi,lo) per k
    __shared__ __align__(16) uint2 Bs[128][AW];   // n-major, (hi,lo) per k

    const int tid    = threadIdx.x;
    const int lane   = tid & 31;
    const int g      = lane >> 2;
    const int t4     = lane & 3;
    const int wid    = tid >> 5;
    const int warp_m = wid & 1;
    const int warp_n = wid >> 1;
    const int lr     = tid >> 2;        // 0..63 loader row
    const int lk     = (tid & 3) << 2;  // 0,4,8,12 loader k offset

    float acc[4][4][4] = {};

    const float* Ap0 = A + (size_t)(m0 + lr)      * lda + lk;
    const float* Ap1 = A + (size_t)(m0 + 64 + lr) * lda + lk;
    const float* Bp0 = B + (size_t)(n0 + lr)      * ldb + lk;
    const float* Bp1 = B + (size_t)(n0 + 64 + lr) * ldb + lk;

    float4 a0 = *(const float4*)(Ap0);
    float4 a1 = *(const float4*)(Ap1);
    float4 b0 = *(const float4*)(Bp0);
    float4 b1 = *(const float4*)(Bp1);

    for (int k0 = 0; k0 < K; k0 += 16) {
        __syncthreads();   // previous iteration's compute done reading smem
        split_store4(&As[lr][lk],      a0);
        split_store4(&As[lr + 64][lk], a1);
        split_store4(&Bs[lr][lk],      b0);
        split_store4(&Bs[lr + 64][lk], b1);
        __syncthreads();

        if (k0 + 16 < K) {     // prefetch next chunk; overlaps with MMAs below
            a0 = *(const float4*)(Ap0 + k0 + 16);
            a1 = *(const float4*)(Ap1 + k0 + 16);
            b0 = *(const float4*)(Bp0 + k0 + 16);
            b1 = *(const float4*)(Bp1 + k0 + 16);
        }

        mma_compute_mn(As, Bs, acc, warp_m, warp_n, g, t4);
    }
    mma_tile_store(C, ldc, m0, n0, acc, warp_m, warp_n, lane, scale);
}

// ---------------------------------------------------------------------------
// Kernel 1: Q/K/V projections. y = x @ W^T (W row-major [out,in] => K-major)
// ---------------------------------------------------------------------------
__global__ void __launch_bounds__(256, 2)
proj_kernel(const float* __restrict__ q, const float* __restrict__ k,
            const float* __restrict__ v, const float* __restrict__ wq,
            const float* __restrict__ wk, const float* __restrict__ wv)
{
    const float* X; const float* W; float* Y;
    if (blockIdx.z == 0)      { X = q; W = wq; Y = g_q; }
    else if (blockIdx.z == 1) { X = k; W = wk; Y = g_k; }
    else                      { X = v; W = wv; Y = g_v; }
    gemm128_kk_mma(X, W, Y, DD, DD, DD, DD, blockIdx.y * 128, blockIdx.x * 128, 1.0f);
}

// ---------------------------------------------------------------------------
// Kernel 2: logits S = (q @ k^T)/sqrt(D); skip tiles above causal diagonal.
// ---------------------------------------------------------------------------
__global__ void __launch_bounds__(256, 2)
scores_kernel()
{
    const int m0 = blockIdx.y * 128;
    const int n0 = blockIdx.x * 128;
    if (n0 > m0) return;               // fully masked tile
    const int n = blockIdx.z;
    gemm128_kk_mma(g_q + (size_t)n * SQ * DD,
                   g_k + (size_t)n * TK * DD,
                   g_s + (size_t)n * SQ * TK,
                   DD, DD, TK, DD, m0, n0, 0.03125f /* 1/sqrt(1024) */);
}

// ---------------------------------------------------------------------------
// Kernel 3: causal row softmax in place; zeros above the diagonal (including
// tiles scores_kernel skipped), so PV can read whole tiles.
// ---------------------------------------------------------------------------
__global__ void __launch_bounds__(256)
softmax_kernel()
{
    __shared__ float red[8];
    const int row = blockIdx.x;             // 0 .. NB*SQ-1
    const int s   = row & (SQ - 1);
    const int len = s + 1;
    float* x = g_s + (size_t)row * TK;
    const int tid = threadIdx.x;

    float vals[TK / 256];
    float m = -3.0e38f;
    #pragma unroll
    for (int i = 0; i < TK / 256; i++) {
        int j = tid + i * 256;
        vals[i] = (j < len) ? x[j] : -3.0e38f;
        m = fmaxf(m, vals[i]);
    }
    #pragma unroll
    for (int o = 16; o; o >>= 1) m = fmaxf(m, __shfl_xor_sync(0xffffffffu, m, o));
    if ((tid & 31) == 0) red[tid >> 5] = m;
    __syncthreads();
    m = red[0];
    #pragma unroll
    for (int w = 1; w < 8; w++) m = fmaxf(m, red[w]);
    __syncthreads();

    float sum = 0.f;
    #pragma unroll
    for (int i = 0; i < TK / 256; i++) {
        int j = tid + i * 256;
        float e = (j < len) ? expf(vals[i] - m) : 0.f;
        vals[i] = e;
        sum += e;
    }
    #pragma unroll
    for (int o = 16; o; o >>= 1) sum += __shfl_xor_sync(0xffffffffu, sum, o);
    if ((tid & 31) == 0) red[tid >> 5] = sum;
    __syncthreads();
    float tot = red[0];
    #pragma unroll
    for (int w = 1; w < 8; w++) tot += red[w];
    const float inv = 1.0f / tot;

    #pragma unroll
    for (int i = 0; i < TK / 256; i++) {
        int j = tid + i * 256;
        x[j] = vals[i] * inv;
    }
}

// ---------------------------------------------------------------------------
// Kernel 4: O = P @ V. P=[SQ,TK] K-major -> As m-major; V=[TK,DD] k-major
// smem Bs[16][132] (read banks (4t4+g) mod 16: bijective, conflict-free).
// K-loop stops at m0+128 (probs beyond are exactly 0).
// ---------------------------------------------------------------------------
__global__ void __launch_bounds__(256, 2)
pv_kernel(float* __restrict__ out)
{
    __shared__ __align__(16) uint2 As[128][AW];   // m-major (hi,lo)
    __shared__ __align__(16) uint2 Bs[16][132];   // k-major (hi,lo)

    const int n  = blockIdx.z;
    const int m0 = blockIdx.y * 128;
    const int n0 = blockIdx.x * 128;
    const float* A = g_s + (size_t)n * SQ * TK;
    const float* B = g_v + (size_t)n * TK * DD;
    float*       C = out + (size_t)n * SQ * DD;
    const int Kend = m0 + 128;

    const int tid    = threadIdx.x;
    const int lane   = tid & 31;
    const int g      = lane >> 2;
    const int t4     = lane & 3;
    const int wid    = tid >> 5;
    const int warp_m = wid & 1;
    const int warp_n = wid >> 1;
    const int lr     = tid >> 2;
    const int lk     = (tid & 3) << 2;
    const int br     = tid >> 5;         // 0..7
    const int bc     = (tid & 31) << 2;  // 0..124

    float acc[4][4][4] = {};

    const float* Ap0 = A + (size_t)(m0 + lr)      * TK + lk;
    const float* Ap1 = A + (size_t)(m0 + 64 + lr) * TK + lk;
    const float* Bp0 = B + (size_t)br       * DD + n0 + bc;
    const float* Bp1 = B + (size_t)(br + 8) * DD + n0 + bc;

    float4 a0 = *(const float4*)(Ap0);
    float4 a1 = *(const float4*)(Ap1);
    float4 v0 = *(const float4*)(Bp0);
    float4 v1 = *(const float4*)(Bp1);

    for (int k0 = 0; k0 < Kend; k0 += 16) {
        __syncthreads();
        split_store4(&As[lr][lk],      a0);
        split_store4(&As[lr + 64][lk], a1);
        split_store4(&Bs[br][bc],      v0);
        split_store4(&Bs[br + 8][bc],  v1);
        __syncthreads();

        if (k0 + 16 < Kend) {   // prefetch next chunk
            a0 = *(const float4*)(Ap0 + k0 + 16);
            a1 = *(const float4*)(Ap1 + k0 + 16);
            v0 = *(const float4*)(Bp0 + (size_t)(k0 + 16) * DD);
            v1 = *(const float4*)(Bp1 + (size_t)(k0 + 16) * DD);
        }

        // inline compute with k-major B
        #pragma unroll
        for (int k8 = 0; k8 < 16; k8 += 8) {
            uint2 b0[4], b1[4];
            #pragma unroll
            for (int j = 0; j < 4; j++) {
                const int nn = warp_n * 32 + j * 8 + g;
                b0[j] = Bs[k8 + t4][nn];
                b1[j] = Bs[k8 + t4 + 4][nn];
            }
            #pragma unroll
            for (int i = 0; i < 4; i++) {
                const int m = warp_m * 64 + i * 16;
                uint2 fa0 = As[m + g][k8 + t4];
                uint2 fa1 = As[m + g + 8][k8 + t4];
                uint2 fa2 = As[m + g][k8 + t4 + 4];
                uint2 fa3 = As[m + g + 8][k8 + t4 + 4];
                #pragma unroll
                for (int j = 0; j < 4; j++) {
                    MMA_TF32(acc[i][j], fa0.y, fa1.y, fa2.y, fa3.y, b0[j].x, b1[j].x);
                    MMA_TF32(acc[i][j], fa0.x, fa1.x, fa2.x, fa3.x, b0[j].y, b1[j].y);
                    MMA_TF32(acc[i][j], fa0.x, fa1.x, fa2.x, fa3.x, b0[j].x, b1[j].x);
                }
            }
        }
    }
    mma_tile_store(C, DD, m0, n0, acc, warp_m, warp_n, lane, 1.0f);
}

// ---------------------------------------------------------------------------
// Inputs (metadata order): query, key, value, attn_mask (int32 tril — causal
// by construction, handled analytically), Wq, Wk, Wv. Output fp32 [4,2048,1024].
// ---------------------------------------------------------------------------
extern "C" void kernel_launch(void* const* d_in, const int* in_sizes, int n_in,
                              void* d_out, int out_size)
{
    const float* q  = (const float*)d_in[0];
    const float* k  = (const float*)d_in[1];
    const float* v  = (const float*)d_in[2];
    const float* wq = (const float*)d_in[4];
    const float* wk = (const float*)d_in[5];
    const float* wv = (const float*)d_in[6];
    float* out = (float*)d_out;

    proj_kernel<<<dim3(DD / 128, (NB * SQ) / 128, 3), 256>>>(q, k, v, wq, wk, wv);
    scores_kernel<<<dim3(TK / 128, SQ / 128, NB), 256>>>();
    softmax_kernel<<<dim3(NB * SQ), 256>>>();
    pv_kernel<<<dim3(DD / 128, SQ / 128, NB), 256>>>(out);
}